// round 8
// baseline (speedup 1.0000x reference)
#include <cuda_runtime.h>
#include <cstdint>

// ---------------------------------------------------------------------------
// MultiheadRCDA: row-column decoupled attention.  E=256, NH=8, HD=32,
// N=8, L=300, H=W=96.
//
// Round 8:
//  - fused stage-1 launch: mean || vproj || q_row-proj || q_col-proj in ONE
//    kernel (block-ID dispatch, mean/vproj interleaved 1:1)
//  - attend: round-6 direct accumulation (measured better) + round-7 LDS.64
//    B loads from pre-permuted vpt
//  - k-proj as small dedicated launch; GEMM body on dynamic smem
// ---------------------------------------------------------------------------

#define NB   8
#define LL   300
#define HH   96
#define WW   96
#define EE   256
#define NHD  8
#define HDD  32

__device__ float g_krm[NB*WW*EE];
__device__ float g_kcm[NB*HH*EE];
__device__ float g_qr [NB*LL*EE];
__device__ float g_qc [NB*LL*EE];
__device__ float g_krp[NB*WW*EE];
__device__ float g_kcp[NB*HH*EE];
__device__ float g_vpt[NB*HH*NHD*HDD*WW];   // [n][h][e][d][w-permuted]
__device__ float g_arow[NB*NHD*LL*WW];
__device__ float g_acol[NB*NHD*LL*HH];
__device__ float g_attn[LL*NB*EE];          // rows ordered l*8+n

__device__ __forceinline__ uint32_t f2b(float x) { return __float_as_uint(x); }

__device__ __forceinline__ void mma_tf32(float* c,
                                         uint32_t a0, uint32_t a1, uint32_t a2, uint32_t a3,
                                         uint32_t b0, uint32_t b1)
{
    asm("mma.sync.aligned.m16n8k8.row.col.f32.tf32.tf32.f32 "
        "{%0,%1,%2,%3}, {%4,%5,%6,%7}, {%8,%9}, {%0,%1,%2,%3};"
        : "+f"(c[0]), "+f"(c[1]), "+f"(c[2]), "+f"(c[3])
        : "r"(a0), "r"(a1), "r"(a2), "r"(a3), "r"(b0), "r"(b1));
}

__device__ __forceinline__ float cvt_tf32_rna(float x)
{
    uint32_t t;
    asm("cvt.rna.tf32.f32 %0, %1;" : "=r"(t) : "f"(x));
    return __uint_as_float(t);
}

__device__ __forceinline__ void cp_async16(uint32_t dst_smem, const void* src)
{
    asm volatile("cp.async.cg.shared.global [%0], [%1], 16;" :: "r"(dst_smem), "l"(src));
}

// ---------------------------------------------------------------------------
// mean block (device func): mb in [0,1536)
// ---------------------------------------------------------------------------
__device__ __forceinline__ void mean_block(int mb,
                                           const float* __restrict__ key_row,
                                           const float* __restrict__ key_col,
                                           float* __restrict__ krm,
                                           float* __restrict__ kcm)
{
    int idx  = mb % 96;
    int rest = mb / 96;
    int which = rest & 1;
    int n     = rest >> 1;
    int e = threadIdx.x;
    float s = 0.f;
    if (which == 0) {
        const float* p = key_row + ((size_t)n*HH*WW + idx) * EE + e;
        #pragma unroll 8
        for (int h = 0; h < HH; ++h) s += p[(size_t)h*WW*EE];
        krm[(n*WW + idx)*EE + e] = s * (1.f/96.f);
    } else {
        const float* p = key_col + ((size_t)(n*HH + idx)*WW) * EE + e;
        #pragma unroll 8
        for (int w = 0; w < WW; ++w) s += p[(size_t)w*EE];
        kcm[(n*HH + idx)*EE + e] = s * (1.f/96.f);
    }
}

// ---------------------------------------------------------------------------
// Unified tf32 GEMM body (register-prefetch pipelined, dynamic smem).
// K=256.  256 threads = 4M x 2N warps; block tile 128 x BN; BK=32.
// smem use: xh[4608] (+ xl[4608] if SPLIT) + ws[BN*36].
// ---------------------------------------------------------------------------
template<int SPLIT, int ROUND, int VPT, int BN>
__device__ __forceinline__ void gemm_tf32_body(const float* __restrict__ X,
                                               const float* __restrict__ W,
                                               const float* __restrict__ bias,
                                               float* __restrict__ Y,
                                               int M, float scale,
                                               int tile_y, int tile_x,
                                               float* smem)
{
    constexpr int WT = BN/32;
    constexpr int NT = BN/16;

    float* xh = smem;
    float* xl = smem + 4608;
    float* ws = smem + (SPLIT ? 9216 : 4608);

    int tid  = threadIdx.x;
    int lane = tid & 31, wid = tid >> 5;
    int wm = wid & 3, wn = wid >> 2;
    int row0 = tile_y * 128, col0 = tile_x * BN;
    int r4 = lane >> 2;
    int j  = lane & 3;

    int lrow = tid >> 3;
    int kq4  = (tid & 7) * 4;
    int sb   = (kq4>>3)*8 + ((kq4&4)>>2);

    float4 xr[4], wr[WT];

    #pragma unroll
    for (int t = 0; t < 4; ++t) {
        int row = row0 + lrow + t*32;
        xr[t] = make_float4(0.f,0.f,0.f,0.f);
        if (row < M) xr[t] = *(const float4*)(X + (size_t)row*256 + kq4);
    }
    #pragma unroll
    for (int t = 0; t < WT; ++t)
        wr[t] = *(const float4*)(W + (size_t)(col0 + lrow + t*32)*256 + kq4);

    float c[2][NT][4] = {};

    for (int k0 = 0; k0 < 256; k0 += 32) {
        __syncthreads();
        #pragma unroll
        for (int t = 0; t < 4; ++t) {
            int base = (lrow + t*32)*36 + sb;
            float vv[4] = {xr[t].x, xr[t].y, xr[t].z, xr[t].w};
            #pragma unroll
            for (int cc = 0; cc < 4; ++cc) {
                float x = vv[cc];
                if (SPLIT) {
                    float hi = __uint_as_float(__float_as_uint(x) & 0xffffe000u);
                    xh[base + cc*2] = hi;
                    xl[base + cc*2] = x - hi;
                } else {
                    xh[base + cc*2] = cvt_tf32_rna(x);
                }
            }
        }
        #pragma unroll
        for (int t = 0; t < WT; ++t) {
            int base = (lrow + t*32)*36 + sb;
            float vv[4] = {wr[t].x, wr[t].y, wr[t].z, wr[t].w};
            #pragma unroll
            for (int cc = 0; cc < 4; ++cc)
                ws[base + cc*2] = cvt_tf32_rna(vv[cc]);
        }
        __syncthreads();

        if (k0 < 224) {
            int kn = k0 + 32;
            #pragma unroll
            for (int t = 0; t < 4; ++t) {
                int row = row0 + lrow + t*32;
                xr[t] = make_float4(0.f,0.f,0.f,0.f);
                if (row < M) xr[t] = *(const float4*)(X + (size_t)row*256 + kn + kq4);
            }
            #pragma unroll
            for (int t = 0; t < WT; ++t)
                wr[t] = *(const float4*)(W + (size_t)(col0 + lrow + t*32)*256 + kn + kq4);
        }

        #pragma unroll
        for (int s = 0; s < 4; ++s) {
            uint32_t b[NT][2];
            #pragma unroll
            for (int nt = 0; nt < NT; ++nt) {
                float2 bb = *(const float2*)(ws + (wn*(BN/2) + nt*8 + r4)*36 + s*8 + j*2);
                b[nt][0] = f2b(bb.x); b[nt][1] = f2b(bb.y);
            }
            #pragma unroll
            for (int mt = 0; mt < 2; ++mt) {
                int rr = wm*32 + mt*16 + r4;
                float2 h0 = *(const float2*)(xh + rr*36      + s*8 + j*2);
                float2 h1 = *(const float2*)(xh + (rr+8)*36  + s*8 + j*2);
                uint32_t ah0=f2b(h0.x), ah1=f2b(h1.x), ah2=f2b(h0.y), ah3=f2b(h1.y);
                #pragma unroll
                for (int nt = 0; nt < NT; ++nt)
                    mma_tf32(c[mt][nt], ah0,ah1,ah2,ah3, b[nt][0], b[nt][1]);
                if (SPLIT) {
                    float2 l0 = *(const float2*)(xl + rr*36      + s*8 + j*2);
                    float2 l1 = *(const float2*)(xl + (rr+8)*36  + s*8 + j*2);
                    uint32_t al0=f2b(l0.x), al1=f2b(l1.x), al2=f2b(l0.y), al3=f2b(l1.y);
                    #pragma unroll
                    for (int nt = 0; nt < NT; ++nt)
                        mma_tf32(c[mt][nt], al0,al1,al2,al3, b[nt][0], b[nt][1]);
                }
            }
        }
    }

    #pragma unroll
    for (int mt = 0; mt < 2; ++mt) {
        int rr = row0 + wm*32 + mt*16 + r4;
        int n0, h0r, wp0, n1, h1r, wp1;
        if (VPT) {
            n0 = rr / 9216; int rem0 = rr - n0*9216; h0r = rem0 / 96;
            int w0r = rem0 - h0r*96;
            wp0 = (w0r & ~7) + ((w0r & 3) << 1) + ((w0r >> 2) & 1);
            int rb = rr + 8;
            n1 = rb / 9216; int rem1 = rb - n1*9216; h1r = rem1 / 96;
            int w1r = rem1 - h1r*96;
            wp1 = (w1r & ~7) + ((w1r & 3) << 1) + ((w1r >> 2) & 1);
        }
        #pragma unroll
        for (int nt = 0; nt < NT; ++nt) {
            int col = col0 + wn*(BN/2) + nt*8 + j*2;
            float2 bv = *(const float2*)(bias + col);
            float o0 = (c[mt][nt][0] + bv.x)*scale, o1 = (c[mt][nt][1] + bv.y)*scale;
            float o2 = (c[mt][nt][2] + bv.x)*scale, o3 = (c[mt][nt][3] + bv.y)*scale;
            if (ROUND) {
                o0 = cvt_tf32_rna(o0); o1 = cvt_tf32_rna(o1);
                o2 = cvt_tf32_rna(o2); o3 = cvt_tf32_rna(o3);
            }
            if (VPT) {
                int e = col >> 5, d = col & 31;
                size_t b0 = (((size_t)(n0*96 + h0r)*8 + e)*32 + d)*96 + wp0;
                size_t b1 = (((size_t)(n1*96 + h1r)*8 + e)*32 + d)*96 + wp1;
                Y[b0] = o0; Y[b0 + 96] = o1;
                Y[b1] = o2; Y[b1 + 96] = o3;
            } else {
                if (rr < M)
                    *(float2*)(Y + (size_t)rr*256 + col) = make_float2(o0, o1);
                if (rr + 8 < M)
                    *(float2*)(Y + (size_t)(rr+8)*256 + col) = make_float2(o2, o3);
            }
        }
    }
}

// ---------------------------------------------------------------------------
// Stage-1 fused launch: mean || vproj || q_row || q_col.
// blocks [0,2304): interleaved (even -> mean b/2, odd -> vproj b/2)
// [2304,2688): mean 1152..1535
// [2688,2764): q_row tiles, [2764,2840): q_col tiles
// ---------------------------------------------------------------------------
__global__ void __launch_bounds__(256) fused_stage1(const float* __restrict__ key_row,
                                                    const float* __restrict__ key_col,
                                                    const float* __restrict__ value,
                                                    const float* __restrict__ query_row,
                                                    const float* __restrict__ query_col,
                                                    const float* __restrict__ ipw,
                                                    const float* __restrict__ ipb,
                                                    float* __restrict__ krm,
                                                    float* __restrict__ kcm,
                                                    float* __restrict__ vpt,
                                                    float* __restrict__ qr,
                                                    float* __restrict__ qc,
                                                    float qscale)
{
    extern __shared__ float sm1[];
    int b = blockIdx.x;
    if (b < 2304) {
        if ((b & 1) == 0) {
            mean_block(b >> 1, key_row, key_col, krm, kcm);
        } else {
            int v = b >> 1;
            gemm_tf32_body<0,1,1,128>(value, ipw + 4*EE*EE, ipb + 4*EE, vpt,
                                      73728, 1.f, v >> 1, v & 1, sm1);
        }
    } else if (b < 2688) {
        mean_block(1152 + (b - 2304), key_row, key_col, krm, kcm);
    } else if (b < 2764) {
        int t = b - 2688;
        gemm_tf32_body<1,0,0,64>(query_row, ipw, ipb, qr,
                                 2400, qscale, t >> 2, t & 3, sm1);
    } else {
        int t = b - 2764;
        gemm_tf32_body<1,0,0,64>(query_col, ipw + EE*EE, ipb + EE, qc,
                                 2400, qscale, t >> 2, t & 3, sm1);
    }
}

// ---------------------------------------------------------------------------
// Stage-2: k projections (need mean).  grid (4, 12).
// ---------------------------------------------------------------------------
__global__ void __launch_bounds__(256) kproj_kernel(const float* __restrict__ krm,
                                                    const float* __restrict__ kcm,
                                                    const float* __restrict__ ipw,
                                                    const float* __restrict__ ipb,
                                                    float* __restrict__ krp,
                                                    float* __restrict__ kcp)
{
    extern __shared__ float sm1[];
    int by = blockIdx.y;
    if (by < 6)
        gemm_tf32_body<1,0,0,64>(krm, ipw + 2*EE*EE, ipb + 2*EE, krp,
                                 768, 1.f, by, blockIdx.x, sm1);
    else
        gemm_tf32_body<1,0,0,64>(kcm, ipw + 3*EE*EE, ipb + 3*EE, kcp,
                                 768, 1.f, by - 6, blockIdx.x, sm1);
}

// out projection
__global__ void __launch_bounds__(256) gemm_tf32_kernel(const float* __restrict__ X,
                                                        const float* __restrict__ W,
                                                        const float* __restrict__ bias,
                                                        float* __restrict__ Y,
                                                        int M, float scale)
{
    extern __shared__ float sm1[];
    gemm_tf32_body<1,0,0,64>(X, W, bias, Y, M, scale, blockIdx.y, blockIdx.x, sm1);
}

// ---------------------------------------------------------------------------
// K4: scores + softmax.  Block per (head, which, n x ltile); K-slice in smem.
// ---------------------------------------------------------------------------
#define SC_LT 5
__global__ void __launch_bounds__(256) scores_kernel(const float* __restrict__ qr,
                                                     const float* __restrict__ krp,
                                                     float* __restrict__ arow,
                                                     const float* __restrict__ qc,
                                                     const float* __restrict__ kcp,
                                                     float* __restrict__ acol)
{
    __shared__ float k_s[32][97];

    int head = blockIdx.x, which = blockIdx.y;
    int n = blockIdx.z / SC_LT, lt = blockIdx.z - n*SC_LT;
    const float* qp   = which ? qc   : qr;
    const float* kp   = which ? kcp  : krp;
    float*       aout = which ? acol : arow;

    int tid = threadIdx.x;
    #pragma unroll
    for (int p = 0; p < 3; ++p) {
        int x  = p*32 + (tid >> 3);
        int d4 = (tid & 7) * 4;
        float4 v = *(const float4*)(kp + ((size_t)(n*96 + x))*256 + head*32 + d4);
        k_s[d4+0][x] = v.x; k_s[d4+1][x] = v.y;
        k_s[d4+2][x] = v.z; k_s[d4+3][x] = v.w;
    }
    __syncthreads();

    int wid = tid >> 5, lane = tid & 31;
    int lend = lt*60 + 60;
    int lbeg = lt*60 + wid*8;
    #pragma unroll 1
    for (int sIt = 0; sIt < 8; sIt += 2) {
        int l0 = lbeg + sIt, l1 = l0 + 1;
        bool v0 = (l0 < lend), v1 = (l1 < lend);
        float q0 = v0 ? qp[((size_t)(n*LL + l0))*256 + head*32 + lane] : 0.f;
        float q1 = v1 ? qp[((size_t)(n*LL + l1))*256 + head*32 + lane] : 0.f;
        float s00=0.f,s01=0.f,s02=0.f, s10=0.f,s11=0.f,s12=0.f;
        #pragma unroll
        for (int d = 0; d < 32; ++d) {
            float qd0 = __shfl_sync(0xffffffffu, q0, d);
            float qd1 = __shfl_sync(0xffffffffu, q1, d);
            float k0 = k_s[d][lane], k1 = k_s[d][lane+32], k2 = k_s[d][lane+64];
            s00 += qd0*k0; s01 += qd0*k1; s02 += qd0*k2;
            s10 += qd1*k0; s11 += qd1*k1; s12 += qd1*k2;
        }
        float m0 = fmaxf(s00, fmaxf(s01, s02));
        float m1 = fmaxf(s10, fmaxf(s11, s12));
        #pragma unroll
        for (int off = 16; off > 0; off >>= 1) {
            m0 = fmaxf(m0, __shfl_xor_sync(0xffffffffu, m0, off));
            m1 = fmaxf(m1, __shfl_xor_sync(0xffffffffu, m1, off));
        }
        float e00 = __expf(s00-m0), e01 = __expf(s01-m0), e02 = __expf(s02-m0);
        float e10 = __expf(s10-m1), e11 = __expf(s11-m1), e12 = __expf(s12-m1);
        float t0 = e00+e01+e02, t1 = e10+e11+e12;
        #pragma unroll
        for (int off = 16; off > 0; off >>= 1) {
            t0 += __shfl_xor_sync(0xffffffffu, t0, off);
            t1 += __shfl_xor_sync(0xffffffffu, t1, off);
        }
        float i0 = 1.f/t0, i1 = 1.f/t1;
        if (v0) {
            float* o = aout + (((size_t)(n*8 + head))*LL + l0)*96;
            o[lane] = e00*i0; o[lane+32] = e01*i0; o[lane+64] = e02*i0;
        }
        if (v1) {
            float* o = aout + (((size_t)(n*8 + head))*LL + l1)*96;
            o[lane] = e10*i1; o[lane+32] = e11*i1; o[lane+64] = e12*i1;
        }
    }
}

// ---------------------------------------------------------------------------
// K5: attend.  Per (n, e, l-tile 64):
//   C[l, d] = sum_{h,w} (acol[l,h]*arow[l,w]) * v[n,h,w,e*32+d]
// 8 warps = 4 M-tiles (m16) x 2-way h-split.  Round-6 direct accumulation
// (rna(product) per MMA) + LDS.64 B loads (pre-permuted vpt, stride 104).
// ---------------------------------------------------------------------------
#define VS_STR  104
#define AR_STR  104
#define AC_STR  97
#define SLAB_F  3328          // 32*VS_STR

__global__ void __launch_bounds__(256) attend_tf32_kernel(const float* __restrict__ arow,
                                                          const float* __restrict__ acol,
                                                          const float* __restrict__ vpt,
                                                          float* __restrict__ attn)
{
    extern __shared__ float sm[];
    float* vs     = sm;                        // 4*3328 = 13312
    float* arow_s = sm + 13312;                // 64*104 = 6656
    float* acol_s = sm + 13312 + 6656;         // 64*97  = 6208
    float* red    = vs;                        // reused after main loop

    int lt = blockIdx.x, e = blockIdx.y, n = blockIdx.z;
    int tid = threadIdx.x, lane = tid & 31, wid = tid >> 5;
    int wm = wid & 3, kh = wid >> 2;
    int l0 = lt * 64;
    int r4 = lane >> 2, j = lane & 3;

    uint32_t vs_u = (uint32_t)__cvta_generic_to_shared(vs);
    const float* vbase = vpt + ((size_t)(n*96)*8 + e) * 3072;

    size_t abase = ((size_t)(n*8 + e)) * LL * 96;
    for (int i = tid; i < 64*96; i += 256) {
        int ll = i / 96, x = i - ll*96;
        int lg = l0 + ll;
        float ar = 0.f, ac = 0.f;
        if (lg < LL) {
            ar = arow[abase + (size_t)lg*96 + x];
            ac = acol[abase + (size_t)lg*96 + x];
        }
        int xp = (x & ~7) + ((x & 3) << 1) + ((x >> 2) & 1);
        arow_s[ll*AR_STR + xp] = ar;
        acol_s[ll*AC_STR + x]  = ac;
    }

    #pragma unroll
    for (int t = 0; t < 6; ++t) {
        int cch  = tid + t*256;
        int slab = cch / 768;
        int r    = cch - slab*768;
        int dd   = r / 24;
        int ck   = r - dd*24;
        cp_async16(vs_u + (slab*SLAB_F + dd*VS_STR + ck*4)*4,
                   vbase + (size_t)slab*24576 + dd*96 + ck*4);
    }
    asm volatile("cp.async.commit_group;");

    float c[4][4] = {};

    for (int it = 0; it < 48; ++it) {
        int buf = it & 1;
        if (it + 1 < 48) {
            int nbuf = buf ^ 1;
            #pragma unroll
            for (int t = 0; t < 6; ++t) {
                int cch  = tid + t*256;
                int slab = cch / 768;
                int r    = cch - slab*768;
                int dd   = r / 24;
                int ck   = r - dd*24;
                int h    = (it+1)*2 + slab;
                cp_async16(vs_u + (nbuf*2*SLAB_F + slab*SLAB_F + dd*VS_STR + ck*4)*4,
                           vbase + (size_t)h*24576 + dd*96 + ck*4);
            }
            asm volatile("cp.async.commit_group;");
            asm volatile("cp.async.wait_group 1;");
        } else {
            asm volatile("cp.async.wait_group 0;");
        }
        __syncthreads();

        int h = it*2 + kh;
        const float* vsl = vs + buf*2*SLAB_F + kh*SLAB_F;
        float ach0 = acol_s[(wm*16 +     r4)*AC_STR + h];
        float ach1 = acol_s[(wm*16 + 8 + r4)*AC_STR + h];

        #pragma unroll
        for (int s = 0; s < 12; ++s) {
            float2 a0 = *(const float2*)(arow_s + (wm*16 +     r4)*AR_STR + s*8 + j*2);
            float2 a1 = *(const float2*)(arow_s + (wm*16 + 8 + r4)*AR_STR + s*8 + j*2);
            uint32_t a_0 = f2b(cvt_tf32_rna(ach0 * a0.x));
            uint32_t a_1 = f2b(cvt_tf32_rna(ach1 * a1.x));
            uint32_t a_2 = f2b(cvt_tf32_rna(ach0 * a0.y));
            uint32_t a_3 = f2b(cvt_tf32_rna(ach1 * a1.y));
            #pragma unroll
            for (int nt = 0; nt < 4; ++nt) {
                float2 bb = *(const float2*)(vsl + (nt*8 + r4)*VS_STR + s*8 + j*2);
                mma_tf32(c[nt], a_0, a_1, a_2, a_3, f2b(bb.x), f2b(bb.y));
            }
        }
        __syncthreads();
    }

    if (kh == 1) {
        int rr = wm*16 + r4;
        #pragma unroll
        for (int nt = 0; nt < 4; ++nt) {
            int col = nt*8 + j*2;
            *(float2*)(red + rr*40 + col)     = make_float2(c[nt][0], c[nt][1]);
            *(float2*)(red + (rr+8)*40 + col) = make_float2(c[nt][2], c[nt][3]);
        }
    }
    __syncthreads();
    if (kh == 0) {
        int rr = wm*16 + r4;
        int lg0 = l0 + rr, lg1 = l0 + rr + 8;
        #pragma unroll
        for (int nt = 0; nt < 4; ++nt) {
            int col = nt*8 + j*2;
            float2 r0 = *(const float2*)(red + rr*40 + col);
            float2 r1 = *(const float2*)(red + (rr+8)*40 + col);
            if (lg0 < LL)
                *(float2*)(attn + ((size_t)(lg0*NB + n))*EE + e*HDD + col) =
                    make_float2(c[nt][0] + r0.x, c[nt][1] + r0.y);
            if (lg1 < LL)
                *(float2*)(attn + ((size_t)(lg1*NB + n))*EE + e*HDD + col) =
                    make_float2(c[nt][2] + r1.x, c[nt][3] + r1.y);
        }
    }
}

// ---------------------------------------------------------------------------
// launch
// ---------------------------------------------------------------------------
static inline float* sym_ptr(const void* sym)
{
    void* p = nullptr;
    cudaGetSymbolAddress(&p, sym);
    return (float*)p;
}

extern "C" void kernel_launch(void* const* d_in, const int* in_sizes, int n_in,
                              void* d_out, int out_size)
{
    const float* query_row = (const float*)d_in[0];
    const float* query_col = (const float*)d_in[1];
    const float* key_row   = (const float*)d_in[2];
    const float* key_col   = (const float*)d_in[3];
    const float* value     = (const float*)d_in[4];
    const float* ipw       = (const float*)d_in[5];
    const float* ipb       = (const float*)d_in[6];
    const float* opw       = (const float*)d_in[7];
    const float* opb       = (const float*)d_in[8];
    float* out = (float*)d_out;

    float* krm  = sym_ptr(g_krm);
    float* kcm  = sym_ptr(g_kcm);
    float* qr   = sym_ptr(g_qr);
    float* qc   = sym_ptr(g_qc);
    float* krp  = sym_ptr(g_krp);
    float* kcp  = sym_ptr(g_kcp);
    float* vpt  = sym_ptr(g_vpt);
    float* arow = sym_ptr(g_arow);
    float* acol = sym_ptr(g_acol);
    float* attn = sym_ptr(g_attn);

    const float scale = 0.17677669529663687f;   // 32^-0.5
    const int GEMM_SMEM = 11520 * 4;             // 46080 B (SPLIT path)
    const int ATT_SMEM  = (13312 + 6656 + 6208) * 4;   // 104704 B

    cudaFuncSetAttribute(attend_tf32_kernel,
                         cudaFuncAttributeMaxDynamicSharedMemorySize, ATT_SMEM);

    // 1. fused: mean || vproj || q_row || q_col
    fused_stage1<<<2840, 256, GEMM_SMEM>>>(key_row, key_col, value,
                                           query_row, query_col, ipw, ipb,
                                           krm, kcm, vpt, qr, qc, scale);

    // 2. k projections
    kproj_kernel<<<dim3(4, 12), 256, GEMM_SMEM>>>(krm, kcm, ipw, ipb, krp, kcp);

    // 3. scores + softmax
    scores_kernel<<<dim3(NHD, 2, NB*SC_LT), 256>>>(qr, krp, arow, qc, kcp, acol);

    // 4. attend
    attend_tf32_kernel<<<dim3(5, NHD, NB), 256, ATT_SMEM>>>(arow, acol, vpt, attn);

    // 5. out projection -> d_out (rows l*8+n)
    gemm_tf32_kernel<<<dim3(4, 19), 256, GEMM_SMEM>>>(attn, opw, opb, out, 2400, 1.f);
}

// round 9
// speedup vs baseline: 1.1925x; 1.1925x over previous
#include <cuda_runtime.h>
#include <cstdint>

// ---------------------------------------------------------------------------
// MultiheadRCDA: row-column decoupled attention.  E=256, NH=8, HD=32,
// N=8, L=300, H=W=96.
//
// Round 9:
//  - stream-level concurrency via graph fork/join (events): vproj || (mean ->
//    kproj) || qproj, then scores -> attend -> out_proj on the joined path
//  - kernels: Round-6 set (measured best) + Round-8 attend (LDS.64 B loads
//    from pre-permuted vpt, direct accumulation)
// ---------------------------------------------------------------------------

#define NB   8
#define LL   300
#define HH   96
#define WW   96
#define EE   256
#define NHD  8
#define HDD  32

__device__ float g_krm[NB*WW*EE];
__device__ float g_kcm[NB*HH*EE];
__device__ float g_qr [NB*LL*EE];
__device__ float g_qc [NB*LL*EE];
__device__ float g_krp[NB*WW*EE];
__device__ float g_kcp[NB*HH*EE];
__device__ float g_vpt[NB*HH*NHD*HDD*WW];   // [n][h][e][d][w-permuted]
__device__ float g_arow[NB*NHD*LL*WW];
__device__ float g_acol[NB*NHD*LL*HH];
__device__ float g_attn[LL*NB*EE];          // rows ordered l*8+n

__device__ __forceinline__ uint32_t f2b(float x) { return __float_as_uint(x); }

__device__ __forceinline__ void mma_tf32(float* c,
                                         uint32_t a0, uint32_t a1, uint32_t a2, uint32_t a3,
                                         uint32_t b0, uint32_t b1)
{
    asm("mma.sync.aligned.m16n8k8.row.col.f32.tf32.tf32.f32 "
        "{%0,%1,%2,%3}, {%4,%5,%6,%7}, {%8,%9}, {%0,%1,%2,%3};"
        : "+f"(c[0]), "+f"(c[1]), "+f"(c[2]), "+f"(c[3])
        : "r"(a0), "r"(a1), "r"(a2), "r"(a3), "r"(b0), "r"(b1));
}

__device__ __forceinline__ float cvt_tf32_rna(float x)
{
    uint32_t t;
    asm("cvt.rna.tf32.f32 %0, %1;" : "=r"(t) : "f"(x));
    return __uint_as_float(t);
}

__device__ __forceinline__ void cp_async16(uint32_t dst_smem, const void* src)
{
    asm volatile("cp.async.cg.shared.global [%0], [%1], 16;" :: "r"(dst_smem), "l"(src));
}

// ---------------------------------------------------------------------------
// K1: mean reductions
// ---------------------------------------------------------------------------
__global__ void mean_kernel(const float* __restrict__ key_row,
                            const float* __restrict__ key_col,
                            float* __restrict__ krm,
                            float* __restrict__ kcm)
{
    int idx = blockIdx.x;
    int which = blockIdx.y;
    int n = blockIdx.z;
    int e = threadIdx.x;
    float s = 0.f;
    if (which == 0) {
        const float* p = key_row + ((size_t)n*HH*WW + idx) * EE + e;
        #pragma unroll 8
        for (int h = 0; h < HH; ++h) s += p[(size_t)h*WW*EE];
        krm[(n*WW + idx)*EE + e] = s * (1.f/96.f);
    } else {
        const float* p = key_col + ((size_t)(n*HH + idx)*WW) * EE + e;
        #pragma unroll 8
        for (int w = 0; w < WW; ++w) s += p[(size_t)w*EE];
        kcm[(n*HH + idx)*EE + e] = s * (1.f/96.f);
    }
}

// ---------------------------------------------------------------------------
// Unified tf32 GEMM body (register-prefetch pipelined, static smem).
// K=256.  256 threads = 4M x 2N warps; block tile 128 x BN; BK=32.
// ---------------------------------------------------------------------------
template<int SPLIT, int ROUND, int VPT, int BN>
__device__ __forceinline__ void gemm_tf32_body(const float* __restrict__ X,
                                               const float* __restrict__ W,
                                               const float* __restrict__ bias,
                                               float* __restrict__ Y,
                                               int M, float scale,
                                               int tile_y, int tile_x)
{
    constexpr int WT = BN/32;
    constexpr int NT = BN/16;

    __shared__ float xh[128*36];
    __shared__ float xl[SPLIT ? 128*36 : 1];
    __shared__ float ws[BN*36];

    int tid  = threadIdx.x;
    int lane = tid & 31, wid = tid >> 5;
    int wm = wid & 3, wn = wid >> 2;
    int row0 = tile_y * 128, col0 = tile_x * BN;
    int r4 = lane >> 2;
    int j  = lane & 3;

    int lrow = tid >> 3;
    int kq4  = (tid & 7) * 4;
    int sb   = (kq4>>3)*8 + ((kq4&4)>>2);

    float4 xr[4], wr[WT];

    #pragma unroll
    for (int t = 0; t < 4; ++t) {
        int row = row0 + lrow + t*32;
        xr[t] = make_float4(0.f,0.f,0.f,0.f);
        if (row < M) xr[t] = *(const float4*)(X + (size_t)row*256 + kq4);
    }
    #pragma unroll
    for (int t = 0; t < WT; ++t)
        wr[t] = *(const float4*)(W + (size_t)(col0 + lrow + t*32)*256 + kq4);

    float c[2][NT][4] = {};

    for (int k0 = 0; k0 < 256; k0 += 32) {
        __syncthreads();
        #pragma unroll
        for (int t = 0; t < 4; ++t) {
            int base = (lrow + t*32)*36 + sb;
            float vv[4] = {xr[t].x, xr[t].y, xr[t].z, xr[t].w};
            #pragma unroll
            for (int cc = 0; cc < 4; ++cc) {
                float x = vv[cc];
                if (SPLIT) {
                    float hi = __uint_as_float(__float_as_uint(x) & 0xffffe000u);
                    xh[base + cc*2] = hi;
                    xl[base + cc*2] = x - hi;
                } else {
                    xh[base + cc*2] = cvt_tf32_rna(x);
                }
            }
        }
        #pragma unroll
        for (int t = 0; t < WT; ++t) {
            int base = (lrow + t*32)*36 + sb;
            float vv[4] = {wr[t].x, wr[t].y, wr[t].z, wr[t].w};
            #pragma unroll
            for (int cc = 0; cc < 4; ++cc)
                ws[base + cc*2] = cvt_tf32_rna(vv[cc]);
        }
        __syncthreads();

        if (k0 < 224) {
            int kn = k0 + 32;
            #pragma unroll
            for (int t = 0; t < 4; ++t) {
                int row = row0 + lrow + t*32;
                xr[t] = make_float4(0.f,0.f,0.f,0.f);
                if (row < M) xr[t] = *(const float4*)(X + (size_t)row*256 + kn + kq4);
            }
            #pragma unroll
            for (int t = 0; t < WT; ++t)
                wr[t] = *(const float4*)(W + (size_t)(col0 + lrow + t*32)*256 + kn + kq4);
        }

        #pragma unroll
        for (int s = 0; s < 4; ++s) {
            uint32_t b[NT][2];
            #pragma unroll
            for (int nt = 0; nt < NT; ++nt) {
                float2 bb = *(const float2*)(ws + (wn*(BN/2) + nt*8 + r4)*36 + s*8 + j*2);
                b[nt][0] = f2b(bb.x); b[nt][1] = f2b(bb.y);
            }
            #pragma unroll
            for (int mt = 0; mt < 2; ++mt) {
                int rr = wm*32 + mt*16 + r4;
                float2 h0 = *(const float2*)(xh + rr*36      + s*8 + j*2);
                float2 h1 = *(const float2*)(xh + (rr+8)*36  + s*8 + j*2);
                uint32_t ah0=f2b(h0.x), ah1=f2b(h1.x), ah2=f2b(h0.y), ah3=f2b(h1.y);
                #pragma unroll
                for (int nt = 0; nt < NT; ++nt)
                    mma_tf32(c[mt][nt], ah0,ah1,ah2,ah3, b[nt][0], b[nt][1]);
                if (SPLIT) {
                    float2 l0 = *(const float2*)(xl + rr*36      + s*8 + j*2);
                    float2 l1 = *(const float2*)(xl + (rr+8)*36  + s*8 + j*2);
                    uint32_t al0=f2b(l0.x), al1=f2b(l1.x), al2=f2b(l0.y), al3=f2b(l1.y);
                    #pragma unroll
                    for (int nt = 0; nt < NT; ++nt)
                        mma_tf32(c[mt][nt], al0,al1,al2,al3, b[nt][0], b[nt][1]);
                }
            }
        }
    }

    #pragma unroll
    for (int mt = 0; mt < 2; ++mt) {
        int rr = row0 + wm*32 + mt*16 + r4;
        int n0, h0r, wp0, n1, h1r, wp1;
        if (VPT) {
            n0 = rr / 9216; int rem0 = rr - n0*9216; h0r = rem0 / 96;
            int w0r = rem0 - h0r*96;
            wp0 = (w0r & ~7) + ((w0r & 3) << 1) + ((w0r >> 2) & 1);
            int rb = rr + 8;
            n1 = rb / 9216; int rem1 = rb - n1*9216; h1r = rem1 / 96;
            int w1r = rem1 - h1r*96;
            wp1 = (w1r & ~7) + ((w1r & 3) << 1) + ((w1r >> 2) & 1);
        }
        #pragma unroll
        for (int nt = 0; nt < NT; ++nt) {
            int col = col0 + wn*(BN/2) + nt*8 + j*2;
            float2 bv = *(const float2*)(bias + col);
            float o0 = (c[mt][nt][0] + bv.x)*scale, o1 = (c[mt][nt][1] + bv.y)*scale;
            float o2 = (c[mt][nt][2] + bv.x)*scale, o3 = (c[mt][nt][3] + bv.y)*scale;
            if (ROUND) {
                o0 = cvt_tf32_rna(o0); o1 = cvt_tf32_rna(o1);
                o2 = cvt_tf32_rna(o2); o3 = cvt_tf32_rna(o3);
            }
            if (VPT) {
                int e = col >> 5, d = col & 31;
                size_t b0 = (((size_t)(n0*96 + h0r)*8 + e)*32 + d)*96 + wp0;
                size_t b1 = (((size_t)(n1*96 + h1r)*8 + e)*32 + d)*96 + wp1;
                Y[b0] = o0; Y[b0 + 96] = o1;
                Y[b1] = o2; Y[b1 + 96] = o3;
            } else {
                if (rr < M)
                    *(float2*)(Y + (size_t)rr*256 + col) = make_float2(o0, o1);
                if (rr + 8 < M)
                    *(float2*)(Y + (size_t)(rr+8)*256 + col) = make_float2(o2, o3);
            }
        }
    }
}

__global__ void __launch_bounds__(256) gemm_tf32_kernel(const float* __restrict__ X,
                                                        const float* __restrict__ W,
                                                        const float* __restrict__ bias,
                                                        float* __restrict__ Y,
                                                        int M, float scale)
{
    gemm_tf32_body<1,0,0,64>(X, W, bias, Y, M, scale, blockIdx.y, blockIdx.x);
}

__global__ void __launch_bounds__(256) vproj_kernel(const float* __restrict__ X,
                                                    const float* __restrict__ W,
                                                    const float* __restrict__ bias,
                                                    float* __restrict__ Y)
{
    gemm_tf32_body<0,1,1,128>(X, W, bias, Y, 73728, 1.f, blockIdx.y, blockIdx.x);
}

// q_row/q_col fused: tiles_y = [19,19]
__global__ void __launch_bounds__(256) qproj_kernel(const float* __restrict__ x0,
                                                    const float* __restrict__ x1,
                                                    float* __restrict__ y0,
                                                    float* __restrict__ y1,
                                                    const float* __restrict__ ipw,
                                                    const float* __restrict__ ipb,
                                                    float qscale)
{
    int by = blockIdx.y;
    if (by < 19)
        gemm_tf32_body<1,0,0,64>(x0, ipw, ipb, y0, 2400, qscale, by, blockIdx.x);
    else
        gemm_tf32_body<1,0,0,64>(x1, ipw + EE*EE, ipb + EE, y1, 2400, qscale, by - 19, blockIdx.x);
}

// k projections: grid (4, 12)
__global__ void __launch_bounds__(256) kproj_kernel(const float* __restrict__ krm,
                                                    const float* __restrict__ kcm,
                                                    const float* __restrict__ ipw,
                                                    const float* __restrict__ ipb,
                                                    float* __restrict__ krp,
                                                    float* __restrict__ kcp)
{
    int by = blockIdx.y;
    if (by < 6)
        gemm_tf32_body<1,0,0,64>(krm, ipw + 2*EE*EE, ipb + 2*EE, krp, 768, 1.f, by, blockIdx.x);
    else
        gemm_tf32_body<1,0,0,64>(kcm, ipw + 3*EE*EE, ipb + 3*EE, kcp, 768, 1.f, by - 6, blockIdx.x);
}

// ---------------------------------------------------------------------------
// K4: scores + softmax.  Block per (head, which, n x ltile); K-slice in smem.
// ---------------------------------------------------------------------------
#define SC_LT 5
__global__ void __launch_bounds__(256) scores_kernel(const float* __restrict__ qr,
                                                     const float* __restrict__ krp,
                                                     float* __restrict__ arow,
                                                     const float* __restrict__ qc,
                                                     const float* __restrict__ kcp,
                                                     float* __restrict__ acol)
{
    __shared__ float k_s[32][97];

    int head = blockIdx.x, which = blockIdx.y;
    int n = blockIdx.z / SC_LT, lt = blockIdx.z - n*SC_LT;
    const float* qp   = which ? qc   : qr;
    const float* kp   = which ? kcp  : krp;
    float*       aout = which ? acol : arow;

    int tid = threadIdx.x;
    #pragma unroll
    for (int p = 0; p < 3; ++p) {
        int x  = p*32 + (tid >> 3);
        int d4 = (tid & 7) * 4;
        float4 v = *(const float4*)(kp + ((size_t)(n*96 + x))*256 + head*32 + d4);
        k_s[d4+0][x] = v.x; k_s[d4+1][x] = v.y;
        k_s[d4+2][x] = v.z; k_s[d4+3][x] = v.w;
    }
    __syncthreads();

    int wid = tid >> 5, lane = tid & 31;
    int lend = lt*60 + 60;
    int lbeg = lt*60 + wid*8;
    #pragma unroll 1
    for (int sIt = 0; sIt < 8; sIt += 2) {
        int l0 = lbeg + sIt, l1 = l0 + 1;
        bool v0 = (l0 < lend), v1 = (l1 < lend);
        float q0 = v0 ? qp[((size_t)(n*LL + l0))*256 + head*32 + lane] : 0.f;
        float q1 = v1 ? qp[((size_t)(n*LL + l1))*256 + head*32 + lane] : 0.f;
        float s00=0.f,s01=0.f,s02=0.f, s10=0.f,s11=0.f,s12=0.f;
        #pragma unroll
        for (int d = 0; d < 32; ++d) {
            float qd0 = __shfl_sync(0xffffffffu, q0, d);
            float qd1 = __shfl_sync(0xffffffffu, q1, d);
            float k0 = k_s[d][lane], k1 = k_s[d][lane+32], k2 = k_s[d][lane+64];
            s00 += qd0*k0; s01 += qd0*k1; s02 += qd0*k2;
            s10 += qd1*k0; s11 += qd1*k1; s12 += qd1*k2;
        }
        float m0 = fmaxf(s00, fmaxf(s01, s02));
        float m1 = fmaxf(s10, fmaxf(s11, s12));
        #pragma unroll
        for (int off = 16; off > 0; off >>= 1) {
            m0 = fmaxf(m0, __shfl_xor_sync(0xffffffffu, m0, off));
            m1 = fmaxf(m1, __shfl_xor_sync(0xffffffffu, m1, off));
        }
        float e00 = __expf(s00-m0), e01 = __expf(s01-m0), e02 = __expf(s02-m0);
        float e10 = __expf(s10-m1), e11 = __expf(s11-m1), e12 = __expf(s12-m1);
        float t0 = e00+e01+e02, t1 = e10+e11+e12;
        #pragma unroll
        for (int off = 16; off > 0; off >>= 1) {
            t0 += __shfl_xor_sync(0xffffffffu, t0, off);
            t1 += __shfl_xor_sync(0xffffffffu, t1, off);
        }
        float i0 = 1.f/t0, i1 = 1.f/t1;
        if (v0) {
            float* o = aout + (((size_t)(n*8 + head))*LL + l0)*96;
            o[lane] = e00*i0; o[lane+32] = e01*i0; o[lane+64] = e02*i0;
        }
        if (v1) {
            float* o = aout + (((size_t)(n*8 + head))*LL + l1)*96;
            o[lane] = e10*i1; o[lane+32] = e11*i1; o[lane+64] = e12*i1;
        }
    }
}

// ---------------------------------------------------------------------------
// K5: attend (Round-8 version: direct accumulation + LDS.64 B loads).
// ---------------------------------------------------------------------------
#define VS_STR  104
#define AR_STR  104
#define AC_STR  97
#define SLAB_F  3328          // 32*VS_STR

__global__ void __launch_bounds__(256) attend_tf32_kernel(const float* __restrict__ arow,
                                                          const float* __restrict__ acol,
                                                          const float* __restrict__ vpt,
                                                          float* __restrict__ attn)
{
    extern __shared__ float sm[];
    float* vs     = sm;                        // 4*3328 = 13312
    float* arow_s = sm + 13312;                // 64*104 = 6656
    float* acol_s = sm + 13312 + 6656;         // 64*97  = 6208
    float* red    = vs;                        // reused after main loop

    int lt = blockIdx.x, e = blockIdx.y, n = blockIdx.z;
    int tid = threadIdx.x, lane = tid & 31, wid = tid >> 5;
    int wm = wid & 3, kh = wid >> 2;
    int l0 = lt * 64;
    int r4 = lane >> 2, j = lane & 3;

    uint32_t vs_u = (uint32_t)__cvta_generic_to_shared(vs);
    const float* vbase = vpt + ((size_t)(n*96)*8 + e) * 3072;

    size_t abase = ((size_t)(n*8 + e)) * LL * 96;
    for (int i = tid; i < 64*96; i += 256) {
        int ll = i / 96, x = i - ll*96;
        int lg = l0 + ll;
        float ar = 0.f, ac = 0.f;
        if (lg < LL) {
            ar = arow[abase + (size_t)lg*96 + x];
            ac = acol[abase + (size_t)lg*96 + x];
        }
        int xp = (x & ~7) + ((x & 3) << 1) + ((x >> 2) & 1);
        arow_s[ll*AR_STR + xp] = ar;
        acol_s[ll*AC_STR + x]  = ac;
    }

    #pragma unroll
    for (int t = 0; t < 6; ++t) {
        int cch  = tid + t*256;
        int slab = cch / 768;
        int r    = cch - slab*768;
        int dd   = r / 24;
        int ck   = r - dd*24;
        cp_async16(vs_u + (slab*SLAB_F + dd*VS_STR + ck*4)*4,
                   vbase + (size_t)slab*24576 + dd*96 + ck*4);
    }
    asm volatile("cp.async.commit_group;");

    float c[4][4] = {};

    for (int it = 0; it < 48; ++it) {
        int buf = it & 1;
        if (it + 1 < 48) {
            int nbuf = buf ^ 1;
            #pragma unroll
            for (int t = 0; t < 6; ++t) {
                int cch  = tid + t*256;
                int slab = cch / 768;
                int r    = cch - slab*768;
                int dd   = r / 24;
                int ck   = r - dd*24;
                int h    = (it+1)*2 + slab;
                cp_async16(vs_u + (nbuf*2*SLAB_F + slab*SLAB_F + dd*VS_STR + ck*4)*4,
                           vbase + (size_t)h*24576 + dd*96 + ck*4);
            }
            asm volatile("cp.async.commit_group;");
            asm volatile("cp.async.wait_group 1;");
        } else {
            asm volatile("cp.async.wait_group 0;");
        }
        __syncthreads();

        int h = it*2 + kh;
        const float* vsl = vs + buf*2*SLAB_F + kh*SLAB_F;
        float ach0 = acol_s[(wm*16 +     r4)*AC_STR + h];
        float ach1 = acol_s[(wm*16 + 8 + r4)*AC_STR + h];

        #pragma unroll
        for (int s = 0; s < 12; ++s) {
            float2 a0 = *(const float2*)(arow_s + (wm*16 +     r4)*AR_STR + s*8 + j*2);
            float2 a1 = *(const float2*)(arow_s + (wm*16 + 8 + r4)*AR_STR + s*8 + j*2);
            uint32_t a_0 = f2b(cvt_tf32_rna(ach0 * a0.x));
            uint32_t a_1 = f2b(cvt_tf32_rna(ach1 * a1.x));
            uint32_t a_2 = f2b(cvt_tf32_rna(ach0 * a0.y));
            uint32_t a_3 = f2b(cvt_tf32_rna(ach1 * a1.y));
            #pragma unroll
            for (int nt = 0; nt < 4; ++nt) {
                float2 bb = *(const float2*)(vsl + (nt*8 + r4)*VS_STR + s*8 + j*2);
                mma_tf32(c[nt], a_0, a_1, a_2, a_3, f2b(bb.x), f2b(bb.y));
            }
        }
        __syncthreads();
    }

    if (kh == 1) {
        int rr = wm*16 + r4;
        #pragma unroll
        for (int nt = 0; nt < 4; ++nt) {
            int col = nt*8 + j*2;
            *(float2*)(red + rr*40 + col)     = make_float2(c[nt][0], c[nt][1]);
            *(float2*)(red + (rr+8)*40 + col) = make_float2(c[nt][2], c[nt][3]);
        }
    }
    __syncthreads();
    if (kh == 0) {
        int rr = wm*16 + r4;
        int lg0 = l0 + rr, lg1 = l0 + rr + 8;
        #pragma unroll
        for (int nt = 0; nt < 4; ++nt) {
            int col = nt*8 + j*2;
            float2 r0 = *(const float2*)(red + rr*40 + col);
            float2 r1 = *(const float2*)(red + (rr+8)*40 + col);
            if (lg0 < LL)
                *(float2*)(attn + ((size_t)(lg0*NB + n))*EE + e*HDD + col) =
                    make_float2(c[nt][0] + r0.x, c[nt][1] + r0.y);
            if (lg1 < LL)
                *(float2*)(attn + ((size_t)(lg1*NB + n))*EE + e*HDD + col) =
                    make_float2(c[nt][2] + r1.x, c[nt][3] + r1.y);
        }
    }
}

// ---------------------------------------------------------------------------
// launch — graph fork/join across 3 streams
// ---------------------------------------------------------------------------
static inline float* sym_ptr(const void* sym)
{
    void* p = nullptr;
    cudaGetSymbolAddress(&p, sym);
    return (float*)p;
}

extern "C" void kernel_launch(void* const* d_in, const int* in_sizes, int n_in,
                              void* d_out, int out_size)
{
    const float* query_row = (const float*)d_in[0];
    const float* query_col = (const float*)d_in[1];
    const float* key_row   = (const float*)d_in[2];
    const float* key_col   = (const float*)d_in[3];
    const float* value     = (const float*)d_in[4];
    const float* ipw       = (const float*)d_in[5];
    const float* ipb       = (const float*)d_in[6];
    const float* opw       = (const float*)d_in[7];
    const float* opb       = (const float*)d_in[8];
    float* out = (float*)d_out;

    float* krm  = sym_ptr(g_krm);
    float* kcm  = sym_ptr(g_kcm);
    float* qr   = sym_ptr(g_qr);
    float* qc   = sym_ptr(g_qc);
    float* krp  = sym_ptr(g_krp);
    float* kcp  = sym_ptr(g_kcp);
    float* vpt  = sym_ptr(g_vpt);
    float* arow = sym_ptr(g_arow);
    float* acol = sym_ptr(g_acol);
    float* attn = sym_ptr(g_attn);

    const float scale = 0.17677669529663687f;   // 32^-0.5
    const int ATT_SMEM = (13312 + 6656 + 6208) * 4;   // 104704 B

    cudaFuncSetAttribute(attend_tf32_kernel,
                         cudaFuncAttributeMaxDynamicSharedMemorySize, ATT_SMEM);

    cudaStream_t s1, s2;
    cudaEvent_t e0, e1, e2;
    cudaStreamCreateWithFlags(&s1, cudaStreamNonBlocking);
    cudaStreamCreateWithFlags(&s2, cudaStreamNonBlocking);
    cudaEventCreateWithFlags(&e0, cudaEventDisableTiming);
    cudaEventCreateWithFlags(&e1, cudaEventDisableTiming);
    cudaEventCreateWithFlags(&e2, cudaEventDisableTiming);

    // fork
    cudaEventRecord(e0, 0);
    cudaStreamWaitEvent(s1, e0, 0);
    cudaStreamWaitEvent(s2, e0, 0);

    // stream 0: v projection (biggest GEMM) -> pre-permuted tf32 vpt
    vproj_kernel<<<dim3(2, 576), 256, 0, 0>>>(value, ipw + 4*EE*EE, ipb + 4*EE, vpt);

    // s1: means -> k projections
    mean_kernel<<<dim3(96, 2, NB), 256, 0, s1>>>(key_row, key_col, krm, kcm);
    kproj_kernel<<<dim3(4, 12), 256, 0, s1>>>(krm, kcm, ipw, ipb, krp, kcp);

    // s2: q projections
    qproj_kernel<<<dim3(4, 38), 256, 0, s2>>>(query_row, query_col, qr, qc,
                                              ipw, ipb, scale);

    // scores on s1 after s2 joins
    cudaEventRecord(e2, s2);
    cudaStreamWaitEvent(s1, e2, 0);
    scores_kernel<<<dim3(NHD, 2, NB*SC_LT), 256, 0, s1>>>(qr, krp, arow, qc, kcp, acol);

    // attend on stream 0 after s1 joins (stream 0 already ordered after vproj)
    cudaEventRecord(e1, s1);
    cudaStreamWaitEvent(0, e1, 0);
    attend_tf32_kernel<<<dim3(5, NHD, NB), 256, ATT_SMEM, 0>>>(arow, acol, vpt, attn);

    // out projection -> d_out (rows l*8+n)
    gemm_tf32_kernel<<<dim3(4, 19), 256, 0, 0>>>(attn, opw, opb, out, 2400, 1.f);

    cudaEventDestroy(e0);
    cudaEventDestroy(e1);
    cudaEventDestroy(e2);
    cudaStreamDestroy(s1);
    cudaStreamDestroy(s2);
}